// round 4
// baseline (speedup 1.0000x reference)
#include <cuda_runtime.h>
#include <cuda_fp16.h>
#include <cstdint>

// ---------------------------------------------------------------------------
// out[8192,11008] = x[8192,4096] @ dequant(W)[11008,4096]^T
// W: int8 stored in int32; scales[11008, 32], group=128 along K.
// fp16 scratch prepass + cp.async/ldmatrix/mma.sync.m16n8k16 GEMM.
// Round 4: warp tile 64x64 (8 warps, 256 thr) to halve LDS traffic.
// ---------------------------------------------------------------------------
#define MM 8192
#define NN 11008
#define KK 4096

#define TM 256
#define TN 128
#define KC 64                              // 64 halves = 128B rows
#define KTILES (KK / KC)                   // 64
#define STAGES 4
#define A_BYTES (TM * KC * 2)              // 32768
#define B_BYTES (TN * KC * 2)              // 16384
#define STAGE_BYTES (A_BYTES + B_BYTES)    // 49152
#define SMEM_TOTAL (STAGES * STAGE_BYTES)  // 196608

__device__ __half g_x[(size_t)MM * KK];    // 67 MB
__device__ __half g_w[(size_t)NN * KK];    // 90 MB

// ---------------------------------------------------------------------------
// PTX helpers (baseline PTX, valid on compute_103)
// ---------------------------------------------------------------------------
__device__ __forceinline__ uint32_t smem_u32(const void* p) {
    uint32_t a;
    asm("{ .reg .u64 t; cvta.to.shared.u64 t, %1; cvt.u32.u64 %0, t; }"
        : "=r"(a) : "l"(p));
    return a;
}

__device__ __forceinline__ void cp16(uint32_t dst, const void* src) {
    asm volatile("cp.async.cg.shared.global [%0], [%1], 16;"
                 :: "r"(dst), "l"(src));
}
__device__ __forceinline__ void cp_commit() {
    asm volatile("cp.async.commit_group;" ::: "memory");
}
template <int N>
__device__ __forceinline__ void cp_wait() {
    asm volatile("cp.async.wait_group %0;" :: "n"(N) : "memory");
}

__device__ __forceinline__ void ldsm4(uint32_t* r, uint32_t addr) {
    asm volatile("ldmatrix.sync.aligned.m8n8.x4.shared.b16 {%0,%1,%2,%3}, [%4];"
                 : "=r"(r[0]), "=r"(r[1]), "=r"(r[2]), "=r"(r[3]) : "r"(addr));
}

__device__ __forceinline__ void mma16816(float* d, const uint32_t* a,
                                         const uint32_t* b) {
    asm volatile(
        "mma.sync.aligned.m16n8k16.row.col.f32.f16.f16.f32 "
        "{%0,%1,%2,%3}, {%4,%5,%6,%7}, {%8,%9}, {%0,%1,%2,%3};"
        : "+f"(d[0]), "+f"(d[1]), "+f"(d[2]), "+f"(d[3])
        : "r"(a[0]), "r"(a[1]), "r"(a[2]), "r"(a[3]), "r"(b[0]), "r"(b[1]));
}

// ---------------------------------------------------------------------------
// Prepass 1: x (fp32) -> g_x (fp16). grid 16384 x 256 exact.
// ---------------------------------------------------------------------------
__global__ void __launch_bounds__(256) prep_x_kernel(const float4* __restrict__ x) {
    size_t i = (size_t)blockIdx.x * 256 + threadIdx.x;
    float4 v0 = x[i * 2], v1 = x[i * 2 + 1];
    __half2 h0 = __floats2half2_rn(v0.x, v0.y);
    __half2 h1 = __floats2half2_rn(v0.z, v0.w);
    __half2 h2 = __floats2half2_rn(v1.x, v1.y);
    __half2 h3 = __floats2half2_rn(v1.z, v1.w);
    uint4 o;
    o.x = *reinterpret_cast<uint32_t*>(&h0);
    o.y = *reinterpret_cast<uint32_t*>(&h1);
    o.z = *reinterpret_cast<uint32_t*>(&h2);
    o.w = *reinterpret_cast<uint32_t*>(&h3);
    reinterpret_cast<uint4*>(g_x)[i] = o;
}

// ---------------------------------------------------------------------------
// Prepass 2: g_w[o,k] = fp16(int8(W) * scales[o, k/128]). grid 22016 x 256.
// ---------------------------------------------------------------------------
__global__ void __launch_bounds__(256) prep_w_kernel(const int4* __restrict__ w,
                                                     const float* __restrict__ sc) {
    size_t i = (size_t)blockIdx.x * 256 + threadIdx.x;   // 8-int chunk
    size_t o = i >> 9;
    int c = (int)(i & 511);
    float s = __ldg(&sc[(o << 5) + (c >> 4)]);
    int4 q0 = w[i * 2], q1 = w[i * 2 + 1];
    __half2 h0 = __floats2half2_rn((float)q0.x * s, (float)q0.y * s);
    __half2 h1 = __floats2half2_rn((float)q0.z * s, (float)q0.w * s);
    __half2 h2 = __floats2half2_rn((float)q1.x * s, (float)q1.y * s);
    __half2 h3 = __floats2half2_rn((float)q1.z * s, (float)q1.w * s);
    uint4 out;
    out.x = *reinterpret_cast<uint32_t*>(&h0);
    out.y = *reinterpret_cast<uint32_t*>(&h1);
    out.z = *reinterpret_cast<uint32_t*>(&h2);
    out.w = *reinterpret_cast<uint32_t*>(&h3);
    reinterpret_cast<uint4*>(g_w)[i] = out;
}

// ---------------------------------------------------------------------------
// GEMM. CTA 256x128, 256 threads (8 warps as 4x2 grid of 64x64 warp tiles).
// SMEM rows 128B (64 halves), XOR-16B swizzle; ldmatrix conflict-free.
// ---------------------------------------------------------------------------
__global__ void __launch_bounds__(256, 1) gemm_kernel(float* __restrict__ out) {
    extern __shared__ __align__(1024) char smem[];
    const uint32_t sb = smem_u32(smem);
    const int tid = threadIdx.x;
    const int lid = tid & 31, wid = tid >> 5;
    const int warp_m = wid >> 1, warp_n = wid & 1;   // 4 x 2
    const int m0 = blockIdx.x * TM, n0 = blockIdx.y * TN;

    // ---- cp.async bases. chunk(i) = tid + i*256; row = (tid>>3)+32*i,
    // k4 = tid&7 (const). Swizzle phase (k4 ^ (row&7)) invariant under +32i.
    const int rbase = tid >> 3, k4 = tid & 7;
    const __half* a_src0 = g_x + (size_t)(m0 + rbase) * KK + k4 * 8;
    const __half* b_src0 = g_w + (size_t)(n0 + rbase) * KK + k4 * 8;
    const uint32_t a_dst0 = sb + rbase * 128 + ((k4 ^ (rbase & 7)) << 4);
    const uint32_t b_dst0 = sb + A_BYTES + rbase * 128 + ((k4 ^ (rbase & 7)) << 4);

    auto issue = [&](int kt, int stage) {
        uint32_t so = (uint32_t)stage * STAGE_BYTES;
        size_t ko = (size_t)kt * KC;
#pragma unroll
        for (int i = 0; i < 8; i++)                       // A: 8 rows apart 32
            cp16(a_dst0 + so + i * 4096, a_src0 + ko + (size_t)i * 32 * KK);
#pragma unroll
        for (int i = 0; i < 4; i++)                       // B: 4 rows apart 32
            cp16(b_dst0 + so + i * 4096, b_src0 + ko + (size_t)i * 32 * KK);
        cp_commit();
    };

    // ---- ldmatrix lane geometry ----
    const int lr = lid & 7;
    const int rowA = warp_m * 64 + lr + ((lid >> 3) & 1) * 8;  // + mi*16
    const int kselA = lid >> 4;                                // + 2*ks
    const int rowB = warp_n * 64 + lr + (lid >> 4) * 8;        // + p*16
    const int kselB = (lid >> 3) & 1;                          // + 2*ks

    float acc[4][8][4];
#pragma unroll
    for (int mi = 0; mi < 4; mi++)
#pragma unroll
        for (int ni = 0; ni < 8; ni++)
#pragma unroll
            for (int q = 0; q < 4; q++) acc[mi][ni][q] = 0.f;

    issue(0, 0); issue(1, 1); issue(2, 2);

    int stage = 0;
#pragma unroll 1
    for (int kt = 0; kt < KTILES; kt++) {
        if (kt + 2 < KTILES)      cp_wait<2>();
        else if (kt + 1 < KTILES) cp_wait<1>();
        else                      cp_wait<0>();
        __syncthreads();
        if (kt + 3 < KTILES) issue(kt + 3, (stage + 3) & 3);

        const uint32_t sA = sb + (uint32_t)stage * STAGE_BYTES;
        const uint32_t sB = sA + A_BYTES;
#pragma unroll
        for (int ks = 0; ks < 4; ks++) {
            uint32_t a[4][4], b[8][2];
#pragma unroll
            for (int mi = 0; mi < 4; mi++) {
                uint32_t addr = sA + (uint32_t)(rowA + mi * 16) * 128
                              + ((uint32_t)((2 * ks + kselA) ^ lr) << 4);
                ldsm4(a[mi], addr);
            }
#pragma unroll
            for (int p = 0; p < 4; p++) {
                uint32_t addr = sB + (uint32_t)(rowB + p * 16) * 128
                              + ((uint32_t)((2 * ks + kselB) ^ lr) << 4);
                uint32_t r[4];
                ldsm4(r, addr);
                b[2 * p][0] = r[0];     b[2 * p][1] = r[1];
                b[2 * p + 1][0] = r[2]; b[2 * p + 1][1] = r[3];
            }
#pragma unroll
            for (int mi = 0; mi < 4; mi++)
#pragma unroll
                for (int ni = 0; ni < 8; ni++)
                    mma16816(acc[mi][ni], a[mi], b[ni]);
        }
        stage = (stage + 1) & 3;
    }

    // ---- epilogue: direct fp32 stores ----
    const int g = lid >> 2, t = lid & 3;
#pragma unroll
    for (int mi = 0; mi < 4; mi++) {
        int r0 = m0 + warp_m * 64 + mi * 16 + g;
#pragma unroll
        for (int ni = 0; ni < 8; ni++) {
            int c = n0 + warp_n * 64 + ni * 8 + 2 * t;
            *reinterpret_cast<float2*>(out + (size_t)r0 * NN + c) =
                make_float2(acc[mi][ni][0], acc[mi][ni][1]);
            *reinterpret_cast<float2*>(out + (size_t)(r0 + 8) * NN + c) =
                make_float2(acc[mi][ni][2], acc[mi][ni][3]);
        }
    }
}

// ---------------------------------------------------------------------------
// Host
// ---------------------------------------------------------------------------
extern "C" void kernel_launch(void* const* d_in, const int* in_sizes, int n_in,
                              void* d_out, int out_size) {
    const float* x = (const float*)d_in[0];
    const int*   w = (const int*)d_in[1];
    const float* sc = (const float*)d_in[2];
    float* out = (float*)d_out;

    cudaFuncSetAttribute(gemm_kernel,
                         cudaFuncAttributeMaxDynamicSharedMemorySize, SMEM_TOTAL);

    prep_x_kernel<<<16384, 256>>>(reinterpret_cast<const float4*>(x));
    prep_w_kernel<<<22016, 256>>>(reinterpret_cast<const int4*>(w), sc);
    gemm_kernel<<<dim3(MM / TM, NN / TN), 256, SMEM_TOTAL>>>(out);
}

// round 5
// speedup vs baseline: 1.0378x; 1.0378x over previous
#include <cuda_runtime.h>
#include <cuda_fp16.h>
#include <cstdint>

// ---------------------------------------------------------------------------
// out[8192,11008] = x[8192,4096] @ dequant(W)[11008,4096]^T
// W: int8 stored in int32; scales[11008, 32], group=128 along K.
// fp16 scratch prepass + cp.async/ldmatrix/mma.sync.m16n8k16 GEMM.
// Round 5: R3 config (512 thr, warp 64x32) + 2-chunks-per-barrier pipeline.
// ---------------------------------------------------------------------------
#define MM 8192
#define NN 11008
#define KK 4096

#define TM 256
#define TN 128
#define KC 64                              // 64 halves = 128B rows
#define KTILES (KK / KC)                   // 64
#define STAGES 4
#define A_BYTES (TM * KC * 2)              // 32768
#define B_BYTES (TN * KC * 2)              // 16384
#define STAGE_BYTES (A_BYTES + B_BYTES)    // 49152
#define SMEM_TOTAL (STAGES * STAGE_BYTES)  // 196608

__device__ __half g_x[(size_t)MM * KK];    // 67 MB
__device__ __half g_w[(size_t)NN * KK];    // 90 MB

// ---------------------------------------------------------------------------
// PTX helpers (baseline PTX, valid on compute_103)
// ---------------------------------------------------------------------------
__device__ __forceinline__ uint32_t smem_u32(const void* p) {
    uint32_t a;
    asm("{ .reg .u64 t; cvta.to.shared.u64 t, %1; cvt.u32.u64 %0, t; }"
        : "=r"(a) : "l"(p));
    return a;
}

__device__ __forceinline__ void cp16(uint32_t dst, const void* src) {
    asm volatile("cp.async.cg.shared.global [%0], [%1], 16;"
                 :: "r"(dst), "l"(src));
}
__device__ __forceinline__ void cp_commit() {
    asm volatile("cp.async.commit_group;" ::: "memory");
}
__device__ __forceinline__ void cp_wait_all() {
    asm volatile("cp.async.wait_group 0;" ::: "memory");
}

__device__ __forceinline__ void ldsm4(uint32_t* r, uint32_t addr) {
    asm volatile("ldmatrix.sync.aligned.m8n8.x4.shared.b16 {%0,%1,%2,%3}, [%4];"
                 : "=r"(r[0]), "=r"(r[1]), "=r"(r[2]), "=r"(r[3]) : "r"(addr));
}

__device__ __forceinline__ void mma16816(float* d, const uint32_t* a,
                                         const uint32_t* b) {
    asm volatile(
        "mma.sync.aligned.m16n8k16.row.col.f32.f16.f16.f32 "
        "{%0,%1,%2,%3}, {%4,%5,%6,%7}, {%8,%9}, {%0,%1,%2,%3};"
        : "+f"(d[0]), "+f"(d[1]), "+f"(d[2]), "+f"(d[3])
        : "r"(a[0]), "r"(a[1]), "r"(a[2]), "r"(a[3]), "r"(b[0]), "r"(b[1]));
}

// ---------------------------------------------------------------------------
// Prepass 1: x (fp32) -> g_x (fp16). grid 16384 x 256 exact.
// ---------------------------------------------------------------------------
__global__ void __launch_bounds__(256) prep_x_kernel(const float4* __restrict__ x) {
    size_t i = (size_t)blockIdx.x * 256 + threadIdx.x;
    float4 v0 = x[i * 2], v1 = x[i * 2 + 1];
    __half2 h0 = __floats2half2_rn(v0.x, v0.y);
    __half2 h1 = __floats2half2_rn(v0.z, v0.w);
    __half2 h2 = __floats2half2_rn(v1.x, v1.y);
    __half2 h3 = __floats2half2_rn(v1.z, v1.w);
    uint4 o;
    o.x = *reinterpret_cast<uint32_t*>(&h0);
    o.y = *reinterpret_cast<uint32_t*>(&h1);
    o.z = *reinterpret_cast<uint32_t*>(&h2);
    o.w = *reinterpret_cast<uint32_t*>(&h3);
    reinterpret_cast<uint4*>(g_x)[i] = o;
}

// ---------------------------------------------------------------------------
// Prepass 2: g_w[o,k] = fp16(int8(W) * scales[o, k/128]). grid 22016 x 256.
// ---------------------------------------------------------------------------
__global__ void __launch_bounds__(256) prep_w_kernel(const int4* __restrict__ w,
                                                     const float* __restrict__ sc) {
    size_t i = (size_t)blockIdx.x * 256 + threadIdx.x;   // 8-int chunk
    size_t o = i >> 9;
    int c = (int)(i & 511);
    float s = __ldg(&sc[(o << 5) + (c >> 4)]);
    int4 q0 = w[i * 2], q1 = w[i * 2 + 1];
    __half2 h0 = __floats2half2_rn((float)q0.x * s, (float)q0.y * s);
    __half2 h1 = __floats2half2_rn((float)q0.z * s, (float)q0.w * s);
    __half2 h2 = __floats2half2_rn((float)q1.x * s, (float)q1.y * s);
    __half2 h3 = __floats2half2_rn((float)q1.z * s, (float)q1.w * s);
    uint4 out;
    out.x = *reinterpret_cast<uint32_t*>(&h0);
    out.y = *reinterpret_cast<uint32_t*>(&h1);
    out.z = *reinterpret_cast<uint32_t*>(&h2);
    out.w = *reinterpret_cast<uint32_t*>(&h3);
    reinterpret_cast<uint4*>(g_w)[i] = out;
}

// ---------------------------------------------------------------------------
// GEMM. CTA 256x128, 512 threads (16 warps, 4x4 grid of 64x32 warp tiles).
// SMEM rows 128B (64 halves), XOR-16B swizzle; ldmatrix conflict-free.
// Pipeline: 4 stages, 2 chunks per iteration, 1 barrier per iteration.
// ---------------------------------------------------------------------------
__global__ void __launch_bounds__(512, 1) gemm_kernel(float* __restrict__ out) {
    extern __shared__ __align__(1024) char smem[];
    const uint32_t sb = smem_u32(smem);
    const int tid = threadIdx.x;
    const int lid = tid & 31, wid = tid >> 5;
    const int warp_m = wid >> 2, warp_n = wid & 3;
    const int m0 = blockIdx.x * TM, n0 = blockIdx.y * TN;

    // ---- cp.async bases (A: 4 chunks of 512, B: 2) ----
    const __half* a_src[4]; uint32_t a_dst[4];
#pragma unroll
    for (int i = 0; i < 4; i++) {
        int ch = tid + i * 512;
        int m = ch >> 3, k4 = ch & 7;
        a_src[i] = g_x + (size_t)(m0 + m) * KK + k4 * 8;
        a_dst[i] = sb + m * 128 + ((k4 ^ (m & 7)) << 4);
    }
    const __half* b_src[2]; uint32_t b_dst[2];
#pragma unroll
    for (int i = 0; i < 2; i++) {
        int ch = tid + i * 512;
        int n = ch >> 3, k4 = ch & 7;
        b_src[i] = g_w + (size_t)(n0 + n) * KK + k4 * 8;
        b_dst[i] = sb + A_BYTES + n * 128 + ((k4 ^ (n & 7)) << 4);
    }

    auto issue = [&](int kt) {
        uint32_t so = (uint32_t)(kt & 3) * STAGE_BYTES;
        size_t ko = (size_t)kt * KC;
#pragma unroll
        for (int i = 0; i < 4; i++) cp16(a_dst[i] + so, a_src[i] + ko);
#pragma unroll
        for (int i = 0; i < 2; i++) cp16(b_dst[i] + so, b_src[i] + ko);
        cp_commit();
    };

    // ---- ldmatrix lane geometry ----
    const int lr = lid & 7;
    const int rowA = warp_m * 64 + lr + ((lid >> 3) & 1) * 8;  // + mi*16
    const int kselA = lid >> 4;                                // + 2*ks
    const int rowB = warp_n * 32 + lr + (lid >> 4) * 8;        // + p*16
    const int kselB = (lid >> 3) & 1;                          // + 2*ks

    float acc[4][4][4];
#pragma unroll
    for (int mi = 0; mi < 4; mi++)
#pragma unroll
        for (int ni = 0; ni < 4; ni++)
#pragma unroll
            for (int q = 0; q < 4; q++) acc[mi][ni][q] = 0.f;

    auto compute = [&](int kt) {
        const uint32_t sA = sb + (uint32_t)(kt & 3) * STAGE_BYTES;
        const uint32_t sB = sA + A_BYTES;
#pragma unroll
        for (int ks = 0; ks < 4; ks++) {
            uint32_t a[4][4], b[4][2];
#pragma unroll
            for (int mi = 0; mi < 4; mi++) {
                uint32_t addr = sA + (uint32_t)(rowA + mi * 16) * 128
                              + ((uint32_t)((2 * ks + kselA) ^ lr) << 4);
                ldsm4(a[mi], addr);
            }
#pragma unroll
            for (int p = 0; p < 2; p++) {
                uint32_t addr = sB + (uint32_t)(rowB + p * 16) * 128
                              + ((uint32_t)((2 * ks + kselB) ^ lr) << 4);
                uint32_t r[4];
                ldsm4(r, addr);
                b[2 * p][0] = r[0];     b[2 * p][1] = r[1];
                b[2 * p + 1][0] = r[2]; b[2 * p + 1][1] = r[3];
            }
#pragma unroll
            for (int mi = 0; mi < 4; mi++)
#pragma unroll
                for (int ni = 0; ni < 4; ni++)
                    mma16816(acc[mi][ni], a[mi], b[ni]);
        }
    };

    issue(0); issue(1);

#pragma unroll 1
    for (int kt = 0; kt < KTILES; kt += 2) {
        cp_wait_all();          // chunks kt, kt+1 resident (issued last iter)
        __syncthreads();        // all warps done with stages being overwritten
        if (kt + 2 < KTILES) { issue(kt + 2); issue(kt + 3); }
        compute(kt);
        compute(kt + 1);
    }

    // ---- epilogue: direct fp32 stores ----
    const int g = lid >> 2, t = lid & 3;
#pragma unroll
    for (int mi = 0; mi < 4; mi++) {
        int r0 = m0 + warp_m * 64 + mi * 16 + g;
#pragma unroll
        for (int ni = 0; ni < 4; ni++) {
            int c = n0 + warp_n * 32 + ni * 8 + 2 * t;
            *reinterpret_cast<float2*>(out + (size_t)r0 * NN + c) =
                make_float2(acc[mi][ni][0], acc[mi][ni][1]);
            *reinterpret_cast<float2*>(out + (size_t)(r0 + 8) * NN + c) =
                make_float2(acc[mi][ni][2], acc[mi][ni][3]);
        }
    }
}

// ---------------------------------------------------------------------------
// Host
// ---------------------------------------------------------------------------
extern "C" void kernel_launch(void* const* d_in, const int* in_sizes, int n_in,
                              void* d_out, int out_size) {
    const float* x = (const float*)d_in[0];
    const int*   w = (const int*)d_in[1];
    const float* sc = (const float*)d_in[2];
    float* out = (float*)d_out;

    cudaFuncSetAttribute(gemm_kernel,
                         cudaFuncAttributeMaxDynamicSharedMemorySize, SMEM_TOTAL);

    prep_x_kernel<<<16384, 256>>>(reinterpret_cast<const float4*>(x));
    prep_w_kernel<<<22016, 256>>>(reinterpret_cast<const int4*>(w), sc);
    gemm_kernel<<<dim3(MM / TM, NN / TN), 512, SMEM_TOTAL>>>(out);
}